// round 14
// baseline (speedup 1.0000x reference)
#include <cuda_runtime.h>
#include <math_constants.h>

#define N_    256
#define D_    512
#define Q_    2048
#define C_    1000
#define IMG_  150528   // 3*224*224
#define IMG4_ 37632    // IMG_/4 = 21 * 1792
#define K_    4

// Output layout: labels | probs | images | grads (return order, float32)
#define OFF_LABELS 0
#define OFF_PROBS  (N_)
#define OFF_IMG    (N_ + N_*C_)
#define OFF_GRADS  (N_ + N_*C_ + N_*IMG_)

#define NQCH 4                  // q-chunks (512 q each)
#define NCAND (NQCH * K_)       // 16 candidates per row

// Scratch (no cudaMalloc allowed; overwritten every call => deterministic)
__device__ float4 g_bankT[128 * Q_];     // bankT[cf4][q] : 4 MB, L2-resident
__device__ float  g_cv[N_ * NCAND];      // per-(row,chunk) top-4 candidate values
__device__ int    g_ci[N_ * NCAND];      // ... and their global q indices

// packed f32x2 FMA (ptxas only emits FFMA2 via explicit PTX)
__device__ __forceinline__ void ffma2(unsigned long long& acc,
                                      unsigned long long a,
                                      unsigned long long b) {
    asm("fma.rn.f32x2 %0, %1, %2, %0;" : "+l"(acc) : "l"(a), "l"(b));
}
__device__ __forceinline__ float unpack_sum(unsigned long long v) {
    float lo = __uint_as_float((unsigned)(v & 0xffffffffull));
    float hi = __uint_as_float((unsigned)(v >> 32));
    return lo + hi;
}

// ---------------------------------------------------------------------------
// Kernel 1: transpose bank to bankT[cf4][q] so dist's bank loads are
// warp-coalesced (consecutive q per lane).
// ---------------------------------------------------------------------------
__global__ void transpose_kernel(const float4* __restrict__ bank4) {
    __shared__ float4 tile[32][33];
    const int tx = threadIdx.x & 31;
    const int ty = threadIdx.x >> 5;
    const int qt = blockIdx.x * 32;
    const int ct = blockIdx.y * 32;
    #pragma unroll
    for (int i = 0; i < 4; i++)
        tile[ty + 8 * i][tx] = bank4[(size_t)(qt + ty + 8 * i) * 128 + ct + tx];
    __syncthreads();
    #pragma unroll
    for (int i = 0; i < 4; i++)
        g_bankT[(size_t)(ct + ty + 8 * i) * Q_ + qt + tx] = tile[tx][ty + 8 * i];
}

// ---------------------------------------------------------------------------
// Kernel 2: dist + per-chunk top-4. Grid (4 q-chunks x 32 row-groups) = 128
// blocks, 256 threads. Thread (h = tid>>7, ql = tid&127): rows 4h..4h+3 of
// this 8-row group x q's {qb + ql + 128j, j<4} (qpt=4).
// Crossbar math: broadcast LDS.128 ~4cyc; total LDS = 2.1e6/qpt -> qpt=4
// cuts the measured ~37us crossbar bottleneck to ~9us, overlapping the
// ~10us FMA pipe. rows=8/block keeps bank L2 traffic at 32 x 4MB = 128 MB
// (R11's 4-row/256MB version was the regression cause).
// Per-chunk top-4 (value desc, index asc) extracted in-block; no global
// distance matrix is ever written.
// ---------------------------------------------------------------------------
__global__ void __launch_bounds__(256) dist_kernel(const float4* __restrict__ feats4) {
    __shared__ float4 s_feat[8 * 128];   // 8 rows x 512 floats = 16 KB
    __shared__ float  s_d[8 * 512];      // 8 rows x 512 distances = 16 KB
    __shared__ float  s_inv[8];
    const int tid = threadIdx.x;
    const int lane = tid & 31, w = tid >> 5;
    const int h  = tid >> 7;             // row-half: 0 or 1 (rows 4h..4h+3)
    const int ql = tid & 127;            // local q column
    const int r0 = blockIdx.y * 8;
    const int qb = blockIdx.x * 512;

    #pragma unroll
    for (int i = tid; i < 8 * 128; i += 256)
        s_feat[i] = feats4[(size_t)r0 * 128 + i];
    __syncthreads();

    // feature norms: warp w reduces row w (8 warps, 8 rows)
    {
        float ss = 0.0f;
        #pragma unroll
        for (int c = lane; c < 128; c += 32) {
            float4 v = s_feat[w * 128 + c];
            ss += v.x * v.x + v.y * v.y + v.z * v.z + v.w * v.w;
        }
        #pragma unroll
        for (int o = 16; o > 0; o >>= 1)
            ss += __shfl_xor_sync(0xffffffffu, ss, o);
        if (lane == 0) s_inv[w] = 1.0f / fmaxf(sqrtf(ss), 1e-12f);
    }
    __syncthreads();

    unsigned long long acc[4][4];
    unsigned long long bb[4] = {0ull, 0ull, 0ull, 0ull};
    #pragma unroll
    for (int r = 0; r < 4; r++)
        #pragma unroll
        for (int j = 0; j < 4; j++) acc[r][j] = 0ull;

    const ulonglong2* bT = reinterpret_cast<const ulonglong2*>(g_bankT) + qb + ql;
    const ulonglong2* sf = reinterpret_cast<const ulonglong2*>(s_feat) + (h * 4) * 128;

    #pragma unroll 2
    for (int c = 0; c < 128; c++) {
        const ulonglong2* row = bT + (size_t)c * Q_;
        ulonglong2 b0 = row[0];
        ulonglong2 b1 = row[128];
        ulonglong2 b2 = row[256];
        ulonglong2 b3 = row[384];
        ffma2(bb[0], b0.x, b0.x); ffma2(bb[0], b0.y, b0.y);
        ffma2(bb[1], b1.x, b1.x); ffma2(bb[1], b1.y, b1.y);
        ffma2(bb[2], b2.x, b2.x); ffma2(bb[2], b2.y, b2.y);
        ffma2(bb[3], b3.x, b3.x); ffma2(bb[3], b3.y, b3.y);
        #pragma unroll
        for (int r = 0; r < 4; r++) {
            ulonglong2 f = sf[r * 128 + c];     // broadcast LDS.128 (warp-uniform)
            ffma2(acc[r][0], f.x, b0.x); ffma2(acc[r][0], f.y, b0.y);
            ffma2(acc[r][1], f.x, b1.x); ffma2(acc[r][1], f.y, b1.y);
            ffma2(acc[r][2], f.x, b2.x); ffma2(acc[r][2], f.y, b2.y);
            ffma2(acc[r][3], f.x, b3.x); ffma2(acc[r][3], f.y, b3.y);
        }
    }

    #pragma unroll
    for (int j = 0; j < 4; j++) {
        const float ibn = 1.0f / fmaxf(sqrtf(unpack_sum(bb[j])), 1e-12f);
        #pragma unroll
        for (int r = 0; r < 4; r++) {
            const int row = h * 4 + r;
            s_d[row * 512 + ql + 128 * j] =
                1.0f - unpack_sum(acc[r][j]) * s_inv[row] * ibn;
        }
    }
    __syncthreads();

    // warp w: per-chunk top-4 of row w over 512 values (value desc, idx asc)
    {
        float v[16];
        #pragma unroll
        for (int t = 0; t < 16; t++)
            v[t] = s_d[w * 512 + t * 32 + lane];     // local idx = t*32+lane

        const int out_base = ((r0 + w) * NQCH + blockIdx.x) * K_;
        for (int k = 0; k < K_; k++) {
            float bv = -CUDART_INF_F; int bi = 1 << 30;
            #pragma unroll
            for (int t = 0; t < 16; t++) {
                if (v[t] > bv) { bv = v[t]; bi = t * 32 + lane; } // asc idx: > keeps low
            }
            #pragma unroll
            for (int o = 16; o > 0; o >>= 1) {
                float ov = __shfl_xor_sync(0xffffffffu, bv, o);
                int   oi = __shfl_xor_sync(0xffffffffu, bi, o);
                if (ov > bv || (ov == bv && oi < bi)) { bv = ov; bi = oi; }
            }
            // mask the winner locally (static indexing only)
            #pragma unroll
            for (int t = 0; t < 16; t++)
                if (bi == t * 32 + lane) v[t] = -CUDART_INF_F;
            if (lane == 0) {
                g_cv[out_base + k] = bv;
                g_ci[out_base + k] = qb + bi;
            }
        }
    }
}

// ---------------------------------------------------------------------------
// Kernel 3 (fused): grid (256, 22). Every block first re-derives the global
// top-4 for its row from the 16 per-chunk candidates (warp-0 merge, ~200cyc,
// free under a DRAM-bound kernel). Then:
//   blockIdx.y < 21 : image gather-mean chunk (1792 float4); n is the FAST
//                     grid dim so duplicate neighbor rows hit L2.
//   blockIdx.y == 21: probs mean + argmax label + grads mean for row n.
// ---------------------------------------------------------------------------
__global__ void fused_gather_kernel(const float4* __restrict__ img4,
                                    const float* __restrict__ bank,
                                    const float* __restrict__ probs,
                                    float* __restrict__ out) {
    const int n = blockIdx.x, tid = threadIdx.x;
    const int lane = tid & 31, w = tid >> 5;

    __shared__ int4 s_ii;
    if (w == 0) {
        // candidate indices are globally unique -> mask by index is safe
        float v = (lane < NCAND) ? g_cv[n * NCAND + lane] : -CUDART_INF_F;
        int   i = (lane < NCAND) ? g_ci[n * NCAND + lane] : (1 << 30);
        int win[K_];
        for (int k = 0; k < K_; k++) {
            float bv = v; int bi = i;
            #pragma unroll
            for (int o = 16; o > 0; o >>= 1) {
                float ov = __shfl_xor_sync(0xffffffffu, bv, o);
                int   oi = __shfl_xor_sync(0xffffffffu, bi, o);
                if (ov > bv || (ov == bv && oi < bi)) { bv = ov; bi = oi; }
            }
            if (i == bi) v = -CUDART_INF_F;
            win[k] = bi;
        }
        if (lane == 0) s_ii = make_int4(win[0], win[1], win[2], win[3]);
    }
    __syncthreads();
    const int i0 = s_ii.x, i1 = s_ii.y, i2 = s_ii.z, i3 = s_ii.w;

    if (blockIdx.y < 21) {
        const int base = blockIdx.y * 1792 + tid;
        const float4* p0 = img4 + (size_t)i0 * IMG4_;
        const float4* p1 = img4 + (size_t)i1 * IMG4_;
        const float4* p2 = img4 + (size_t)i2 * IMG4_;
        const float4* p3 = img4 + (size_t)i3 * IMG4_;
        float4* po = reinterpret_cast<float4*>(out + OFF_IMG) + (size_t)n * IMG4_;
        #pragma unroll
        for (int t = 0; t < 7; t++) {
            const int j = base + t * 256;
            float4 a = p0[j];
            float4 b = p1[j];
            float4 c = p2[j];
            float4 d = p3[j];
            float4 r;
            r.x = 0.25f * (a.x + b.x + c.x + d.x);
            r.y = 0.25f * (a.y + b.y + c.y + d.y);
            r.z = 0.25f * (a.z + b.z + c.z + d.z);
            r.w = 0.25f * (a.w + b.w + c.w + d.w);
            __stcs(po + j, r);
        }
    } else {
        // grads mean (512)
        float* outg = out + OFF_GRADS + (size_t)n * D_;
        for (int d = tid; d < D_; d += 256)
            outg[d] = 0.25f * (bank[(size_t)i0 * D_ + d] + bank[(size_t)i1 * D_ + d] +
                               bank[(size_t)i2 * D_ + d] + bank[(size_t)i3 * D_ + d]);
        // probs mean (1000) + argmax -> label
        float* outp = out + OFF_PROBS + (size_t)n * C_;
        float bv = -CUDART_INF_F; int bc = C_;
        for (int c = tid; c < C_; c += 256) {
            float p = 0.25f * (probs[(size_t)i0 * C_ + c] + probs[(size_t)i1 * C_ + c] +
                               probs[(size_t)i2 * C_ + c] + probs[(size_t)i3 * C_ + c]);
            outp[c] = p;
            if (p > bv) { bv = p; bc = c; }          // ascending c per thread
        }
        __shared__ float s_wv[8];
        __shared__ int   s_wi[8];
        #pragma unroll
        for (int o = 16; o > 0; o >>= 1) {
            float ov = __shfl_xor_sync(0xffffffffu, bv, o);
            int   oi = __shfl_xor_sync(0xffffffffu, bc, o);
            if (ov > bv || (ov == bv && oi < bc)) { bv = ov; bc = oi; }
        }
        if (lane == 0) { s_wv[w] = bv; s_wi[w] = bc; }
        __syncthreads();
        if (tid == 0) {
            float v2 = s_wv[0]; int ib = s_wi[0];
            #pragma unroll
            for (int p = 1; p < 8; p++)
                if (s_wv[p] > v2 || (s_wv[p] == v2 && s_wi[p] < ib)) {
                    v2 = s_wv[p]; ib = s_wi[p];
                }
            out[OFF_LABELS + n] = (float)ib;
        }
    }
}

// ---------------------------------------------------------------------------
extern "C" void kernel_launch(void* const* d_in, const int* in_sizes, int n_in,
                              void* d_out, int out_size) {
    const float* feats = (const float*)d_in[0];   // (256, 512)
    const float* bank  = (const float*)d_in[1];   // (2048, 512)
    const float* probs = (const float*)d_in[2];   // (2048, 1000)
    const float* img   = (const float*)d_in[3];   // (2048, 3, 224, 224)
    float* out = (float*)d_out;

    transpose_kernel<<<dim3(Q_ / 32, 128 / 32), 256>>>(
        reinterpret_cast<const float4*>(bank));
    dist_kernel<<<dim3(NQCH, 32), 256>>>(
        reinterpret_cast<const float4*>(feats));
    fused_gather_kernel<<<dim3(N_, 22), 256>>>(
        reinterpret_cast<const float4*>(img), bank, probs, out);
}

// round 15
// speedup vs baseline: 1.2037x; 1.2037x over previous
#include <cuda_runtime.h>
#include <math_constants.h>

#define N_    256
#define D_    512
#define Q_    2048
#define C_    1000
#define IMG_  150528   // 3*224*224
#define IMG4_ 37632    // IMG_/4 = 21 * 1792
#define K_    4

// Output layout: labels | probs | images | grads (return order, float32)
#define OFF_LABELS 0
#define OFF_PROBS  (N_)
#define OFF_IMG    (N_ + N_*C_)
#define OFF_GRADS  (N_ + N_*C_ + N_*IMG_)

#define NQCH 16                 // q-chunks (128 q each)
#define NCAND (NQCH * K_)       // 64 candidates per row

// Scratch (no cudaMalloc allowed; overwritten every call => deterministic)
__device__ float4 g_bankT[128 * Q_];     // bankT[cf4][q] : 4 MB, L2-resident
__device__ float  g_binv[Q_];            // 1/max(||bank_q||, 1e-12)
__device__ float  g_cv[N_ * NCAND];      // per-(row,chunk) top-4 candidate values
__device__ int    g_ci[N_ * NCAND];      // ... and their global q indices

// packed f32x2 FMA (ptxas only emits FFMA2 via explicit PTX)
__device__ __forceinline__ void ffma2(unsigned long long& acc,
                                      unsigned long long a,
                                      unsigned long long b) {
    asm("fma.rn.f32x2 %0, %1, %2, %0;" : "+l"(acc) : "l"(a), "l"(b));
}
__device__ __forceinline__ float unpack_sum(unsigned long long v) {
    float lo = __uint_as_float((unsigned)(v & 0xffffffffull));
    float hi = __uint_as_float((unsigned)(v >> 32));
    return lo + hi;
}

// ---------------------------------------------------------------------------
// Kernel 1: transpose bank to bankT[cf4][q] (coalesced dist loads) AND
// compute bank inverse norms (by==0 blocks; they re-read their 32 rows —
// deterministic, no atomics). 512 threads for latency hiding.
// ---------------------------------------------------------------------------
__global__ void __launch_bounds__(512) transpose_kernel(const float4* __restrict__ bank4) {
    __shared__ float4 tile[32][33];
    const int tx = threadIdx.x & 31;
    const int ty = threadIdx.x >> 5;         // 0..15
    const int qt = blockIdx.x * 32;
    const int ct = blockIdx.y * 32;
    #pragma unroll
    for (int i = 0; i < 2; i++)
        tile[ty + 16 * i][tx] = bank4[(size_t)(qt + ty + 16 * i) * 128 + ct + tx];
    __syncthreads();
    #pragma unroll
    for (int i = 0; i < 2; i++)
        g_bankT[(size_t)(ct + ty + 16 * i) * Q_ + qt + tx] = tile[tx][ty + 16 * i];

    if (blockIdx.y == 0) {
        // 16 warps: warp w reduces rows qt+2w, qt+2w+1
        const int w = ty, lane = tx;
        #pragma unroll
        for (int rr = 2 * w; rr < 2 * w + 2; rr++) {
            float ss = 0.0f;
            #pragma unroll
            for (int c = lane; c < 128; c += 32) {
                float4 v = bank4[(size_t)(qt + rr) * 128 + c];
                ss += v.x * v.x + v.y * v.y + v.z * v.z + v.w * v.w;
            }
            #pragma unroll
            for (int o = 16; o > 0; o >>= 1)
                ss += __shfl_xor_sync(0xffffffffu, ss, o);
            if (lane == 0)
                g_binv[qt + rr] = 1.0f / fmaxf(sqrtf(ss), 1e-12f);
        }
    }
}

// ---------------------------------------------------------------------------
// Kernel 2: dist + per-chunk top-4 (exact R9 structure — the 137.7us champion
// — minus the bank self-dot, which now comes precomputed via g_binv).
// Grid (16 q-chunks x 16 row-groups) = 256 blocks, 256 threads.
// Thread (h = tid>>7, ql = tid&127): rows 8h..8h+7 x q = qb + ql.
// 2 blocks/SM co-resident. Per-chunk top-4 (value desc, index asc)
// extracted in-block; no global distance matrix is ever written.
// ---------------------------------------------------------------------------
__global__ void __launch_bounds__(256) dist_kernel(const float4* __restrict__ feats4) {
    __shared__ float s_mem[16 * 512];    // 32 KB: feats tile, then 16x128 d tile
    __shared__ float s_inv[16];
    const int tid = threadIdx.x;
    const int lane = tid & 31, w = tid >> 5;
    const int h  = tid >> 7;             // row-half: 0 or 1
    const int ql = tid & 127;            // local q
    const int r0 = blockIdx.y * 16;
    const int qb = blockIdx.x * 128;

    float4* s_feat = reinterpret_cast<float4*>(s_mem);   // 16 x 128 float4
    #pragma unroll
    for (int i = tid; i < 16 * 128; i += 256)
        s_feat[i] = feats4[(size_t)r0 * 128 + i];
    __syncthreads();

    // feature norms: warp w reduces rows 2w and 2w+1
    #pragma unroll
    for (int rr = 2 * w; rr < 2 * w + 2; rr++) {
        float ss = 0.0f;
        #pragma unroll
        for (int c = lane; c < 128; c += 32) {
            float4 v = s_feat[rr * 128 + c];
            ss += v.x * v.x + v.y * v.y + v.z * v.z + v.w * v.w;
        }
        #pragma unroll
        for (int o = 16; o > 0; o >>= 1)
            ss += __shfl_xor_sync(0xffffffffu, ss, o);
        if (lane == 0) s_inv[rr] = 1.0f / fmaxf(sqrtf(ss), 1e-12f);
    }
    __syncthreads();

    unsigned long long acc[8];
    #pragma unroll
    for (int r = 0; r < 8; r++) acc[r] = 0ull;

    const ulonglong2* bT = reinterpret_cast<const ulonglong2*>(g_bankT) + qb + ql;
    const ulonglong2* sf = reinterpret_cast<const ulonglong2*>(s_mem) + (h * 8) * 128;

    #pragma unroll 4
    for (int c = 0; c < 128; c++) {
        ulonglong2 b = bT[(size_t)c * Q_];
        #pragma unroll
        for (int r = 0; r < 8; r++) {
            ulonglong2 f = sf[r * 128 + c];       // warp-broadcast LDS.128
            ffma2(acc[r], f.x, b.x);
            ffma2(acc[r], f.y, b.y);
        }
    }

    float d[8];
    const float ibn = g_binv[qb + ql];            // precomputed in transpose
    #pragma unroll
    for (int r = 0; r < 8; r++)
        d[r] = 1.0f - unpack_sum(acc[r]) * s_inv[h * 8 + r] * ibn;

    // store distance tile: s_d[rr * 128 + ql] (warp-contiguous, conflict-free)
    __syncthreads();                      // everyone done reading s_feat
    #pragma unroll
    for (int r = 0; r < 8; r++)
        s_mem[(h * 8 + r) * 128 + ql] = d[r];
    __syncthreads();

    // warp w: per-chunk top-4 of rows 2w and 2w+1 (value desc, index asc)
    #pragma unroll
    for (int rr = 2 * w; rr < 2 * w + 2; rr++) {
        float v[4];
        #pragma unroll
        for (int t = 0; t < 4; t++)
            v[t] = s_mem[rr * 128 + t * 32 + lane];   // local idx = t*32+lane

        const int out_base = ((r0 + rr) * NQCH + blockIdx.x) * K_;
        for (int k = 0; k < K_; k++) {
            float bv = -CUDART_INF_F; int bi = 1 << 30;
            #pragma unroll
            for (int t = 0; t < 4; t++) {
                if (v[t] > bv) { bv = v[t]; bi = t * 32 + lane; } // asc idx: > keeps low
            }
            #pragma unroll
            for (int o = 16; o > 0; o >>= 1) {
                float ov = __shfl_xor_sync(0xffffffffu, bv, o);
                int   oi = __shfl_xor_sync(0xffffffffu, bi, o);
                if (ov > bv || (ov == bv && oi < bi)) { bv = ov; bi = oi; }
            }
            // mask the winner locally (static indexing only)
            #pragma unroll
            for (int t = 0; t < 4; t++)
                if (bi == t * 32 + lane) v[t] = -CUDART_INF_F;
            if (lane == 0) {
                g_cv[out_base + k] = bv;
                g_ci[out_base + k] = qb + bi;
            }
        }
    }
}

// ---------------------------------------------------------------------------
// Kernel 3 (fused): grid (256, 22). Every block first re-derives the global
// top-4 for its row from the 64 per-chunk candidates (warp-0 merge, 2 cands
// per lane, ~250 cyc — free under a DRAM-bound kernel). Then:
//   blockIdx.y < 21 : image gather-mean chunk (1792 float4); n is the FAST
//                     grid dim so duplicate neighbor rows hit L2.
//   blockIdx.y == 21: probs mean + argmax label + grads mean for row n.
// ---------------------------------------------------------------------------
__global__ void fused_gather_kernel(const float4* __restrict__ img4,
                                    const float* __restrict__ bank,
                                    const float* __restrict__ probs,
                                    float* __restrict__ out) {
    const int n = blockIdx.x, tid = threadIdx.x;
    const int lane = tid & 31, w = tid >> 5;

    __shared__ int4 s_ii;
    if (w == 0) {
        // candidate indices are globally unique -> mask by index is safe
        float v0 = g_cv[n * NCAND + lane];
        float v1 = g_cv[n * NCAND + 32 + lane];
        int   c0 = g_ci[n * NCAND + lane];
        int   c1 = g_ci[n * NCAND + 32 + lane];
        int win[K_];
        for (int k = 0; k < K_; k++) {
            float bv; int bi;
            if (v0 > v1 || (v0 == v1 && c0 < c1)) { bv = v0; bi = c0; }
            else                                   { bv = v1; bi = c1; }
            #pragma unroll
            for (int o = 16; o > 0; o >>= 1) {
                float ov = __shfl_xor_sync(0xffffffffu, bv, o);
                int   oi = __shfl_xor_sync(0xffffffffu, bi, o);
                if (ov > bv || (ov == bv && oi < bi)) { bv = ov; bi = oi; }
            }
            if (c0 == bi) v0 = -CUDART_INF_F;
            if (c1 == bi) v1 = -CUDART_INF_F;
            win[k] = bi;
        }
        if (lane == 0) s_ii = make_int4(win[0], win[1], win[2], win[3]);
    }
    __syncthreads();
    const int i0 = s_ii.x, i1 = s_ii.y, i2 = s_ii.z, i3 = s_ii.w;

    if (blockIdx.y < 21) {
        const int base = blockIdx.y * 1792 + tid;
        const float4* p0 = img4 + (size_t)i0 * IMG4_;
        const float4* p1 = img4 + (size_t)i1 * IMG4_;
        const float4* p2 = img4 + (size_t)i2 * IMG4_;
        const float4* p3 = img4 + (size_t)i3 * IMG4_;
        float4* po = reinterpret_cast<float4*>(out + OFF_IMG) + (size_t)n * IMG4_;
        #pragma unroll
        for (int t = 0; t < 7; t++) {
            const int j = base + t * 256;
            float4 a = p0[j];
            float4 b = p1[j];
            float4 c = p2[j];
            float4 d = p3[j];
            float4 r;
            r.x = 0.25f * (a.x + b.x + c.x + d.x);
            r.y = 0.25f * (a.y + b.y + c.y + d.y);
            r.z = 0.25f * (a.z + b.z + c.z + d.z);
            r.w = 0.25f * (a.w + b.w + c.w + d.w);
            __stcs(po + j, r);
        }
    } else {
        // grads mean (512)
        float* outg = out + OFF_GRADS + (size_t)n * D_;
        for (int d = tid; d < D_; d += 256)
            outg[d] = 0.25f * (bank[(size_t)i0 * D_ + d] + bank[(size_t)i1 * D_ + d] +
                               bank[(size_t)i2 * D_ + d] + bank[(size_t)i3 * D_ + d]);
        // probs mean (1000) + argmax -> label
        float* outp = out + OFF_PROBS + (size_t)n * C_;
        float bv = -CUDART_INF_F; int bc = C_;
        for (int c = tid; c < C_; c += 256) {
            float p = 0.25f * (probs[(size_t)i0 * C_ + c] + probs[(size_t)i1 * C_ + c] +
                               probs[(size_t)i2 * C_ + c] + probs[(size_t)i3 * C_ + c]);
            outp[c] = p;
            if (p > bv) { bv = p; bc = c; }          // ascending c per thread
        }
        __shared__ float s_wv[8];
        __shared__ int   s_wi[8];
        #pragma unroll
        for (int o = 16; o > 0; o >>= 1) {
            float ov = __shfl_xor_sync(0xffffffffu, bv, o);
            int   oi = __shfl_xor_sync(0xffffffffu, bc, o);
            if (ov > bv || (ov == bv && oi < bc)) { bv = ov; bc = oi; }
        }
        if (lane == 0) { s_wv[w] = bv; s_wi[w] = bc; }
        __syncthreads();
        if (tid == 0) {
            float v2 = s_wv[0]; int ib = s_wi[0];
            #pragma unroll
            for (int p = 1; p < 8; p++)
                if (s_wv[p] > v2 || (s_wv[p] == v2 && s_wi[p] < ib)) {
                    v2 = s_wv[p]; ib = s_wi[p];
                }
            out[OFF_LABELS + n] = (float)ib;
        }
    }
}

// ---------------------------------------------------------------------------
extern "C" void kernel_launch(void* const* d_in, const int* in_sizes, int n_in,
                              void* d_out, int out_size) {
    const float* feats = (const float*)d_in[0];   // (256, 512)
    const float* bank  = (const float*)d_in[1];   // (2048, 512)
    const float* probs = (const float*)d_in[2];   // (2048, 1000)
    const float* img   = (const float*)d_in[3];   // (2048, 3, 224, 224)
    float* out = (float*)d_out;

    transpose_kernel<<<dim3(Q_ / 32, 128 / 32), 512>>>(
        reinterpret_cast<const float4*>(bank));
    dist_kernel<<<dim3(NQCH, 16), 256>>>(
        reinterpret_cast<const float4*>(feats));
    fused_gather_kernel<<<dim3(N_, 22), 256>>>(
        reinterpret_cast<const float4*>(img), bank, probs, out);
}